// round 11
// baseline (speedup 1.0000x reference)
#include <cuda_runtime.h>
#include <cuda_bf16.h>
#include <cstdint>
#include <math.h>

#define NROWS 8192
#define DIN   512
#define HID   1024
#define EMBD  64
#define NCON  62
#define NCLS  16
#define MARGINF 0.01f
#define OUT_OFF (NROWS * DIN)

// ======================= helpers ================================================
__device__ __forceinline__ void ld16(uint32_t s, const void* g) {
    asm volatile("cp.async.cg.shared.global [%0], [%1], 16;" :: "r"(s), "l"(g));
}
__device__ __forceinline__ uint32_t smem_u32(const void* p) {
    uint32_t a;
    asm("{ .reg .u64 t; cvta.to.shared.u64 t, %1; cvt.u32.u64 %0, t; }" : "=r"(a) : "l"(p));
    return a;
}
__device__ __forceinline__ void ldsm4(uint32_t* r, uint32_t addr) {
    asm volatile("ldmatrix.sync.aligned.m8n8.x4.shared.b16 {%0,%1,%2,%3}, [%4];"
        : "=r"(r[0]), "=r"(r[1]), "=r"(r[2]), "=r"(r[3]) : "r"(addr));
}
__device__ __forceinline__ void mma16816(float* c, const uint32_t* a, const uint32_t* b) {
    asm volatile("mma.sync.aligned.m16n8k16.row.col.f32.bf16.bf16.f32 "
        "{%0,%1,%2,%3}, {%4,%5,%6,%7}, {%8,%9}, {%0,%1,%2,%3};"
        : "+f"(c[0]), "+f"(c[1]), "+f"(c[2]), "+f"(c[3])
        : "r"(a[0]), "r"(a[1]), "r"(a[2]), "r"(a[3]), "r"(b[0]), "r"(b[1]));
}

// ======================= scratch (device globals) ===============================
__device__ __nv_bfloat16 g_data_h[NROWS * DIN],  g_data_l[NROWS * DIN];
__device__ __nv_bfloat16 g_h1_h[NROWS * HID],    g_h1_l[NROWS * HID];
__device__ __nv_bfloat16 g_emb_h[NROWS * EMBD],  g_emb_l[NROWS * EMBD];
__device__ __nv_bfloat16 g_h2_h[NROWS * HID],    g_h2_l[NROWS * HID];
__device__ __nv_bfloat16 g_w1_h[HID * DIN],  g_w1_l[HID * DIN];    // [N,K]
__device__ __nv_bfloat16 g_w2_h[EMBD * HID], g_w2_l[EMBD * HID];
__device__ __nv_bfloat16 g_w3_h[HID * EMBD], g_w3_l[HID * EMBD];
__device__ __nv_bfloat16 g_w4_h[DIN * HID],  g_w4_l[DIN * HID];
__device__ float  g_emb[NROWS * EMBD];
__device__ int    g_lbl[NROWS];
__device__ float  g_sq[NROWS];
__device__ int    g_counts[NCLS], g_off[NCLS], g_cur[NCLS], g_idx[NROWS];
__device__ double g_S[NCLS * NCON];
__device__ double g_Q[NCLS];
__device__ double g_cdiff;
__device__ int    g_ctr[8];   // per-layer persistent tile counters

// ======================= small kernels ==========================================
__global__ void k_init() {
    int t = threadIdx.x;
    if (t < NCLS) { g_counts[t] = 0; g_Q[t] = 0.0; }
    if (t < 8) g_ctr[t] = 0;
    if (t == 0) g_cdiff = 0.0;
    for (int i = t; i < NCLS * NCON; i += blockDim.x) g_S[i] = 0.0;
}

__global__ void k_prep(const float* __restrict__ x) {
    const int total = NROWS * (DIN + 1);
    for (int e = blockIdx.x * blockDim.x + threadIdx.x; e < total;
         e += gridDim.x * blockDim.x) {
        int i = e / (DIN + 1);
        int j = e - i * (DIN + 1);
        float v = x[e];
        if (j == 0) {
            int c = (int)v;
            g_lbl[i] = c;
            atomicAdd(&g_counts[c], 1);
        } else {
            __nv_bfloat16 h = __float2bfloat16(v);
            float lo = v - __bfloat162float(h);
            int idx = i * DIN + (j - 1);
            g_data_h[idx] = h;
            g_data_l[idx] = __float2bfloat16(lo);
        }
    }
}

// transpose + split all four weight matrices W[K,N] -> [N,K] bf16 hi/lo
__global__ void k_wt_all(const float* __restrict__ W1, const float* __restrict__ W2,
                         const float* __restrict__ W3, const float* __restrict__ W4) {
    const int S1 = DIN * HID, S2 = HID * EMBD, S3 = EMBD * HID, S4 = HID * DIN;
    const int T1 = S1, T2 = T1 + S2, T3 = T2 + S3, T4 = T3 + S4;
    for (int e = blockIdx.x * blockDim.x + threadIdx.x; e < T4;
         e += gridDim.x * blockDim.x) {
        const float* W;
        __nv_bfloat16 *th, *tl;
        int le, K, N;
        if (e < T1)      { W = W1; th = g_w1_h; tl = g_w1_l; le = e;      K = DIN;  N = HID;  }
        else if (e < T2) { W = W2; th = g_w2_h; tl = g_w2_l; le = e - T1; K = HID;  N = EMBD; }
        else if (e < T3) { W = W3; th = g_w3_h; tl = g_w3_l; le = e - T2; K = EMBD; N = HID;  }
        else             { W = W4; th = g_w4_h; tl = g_w4_l; le = e - T3; K = HID;  N = DIN;  }
        int k = le / N, n = le - k * N;
        float v = W[le];
        __nv_bfloat16 h = __float2bfloat16(v);
        float lo = v - __bfloat162float(h);
        th[n * K + k] = h;
        tl[n * K + k] = __float2bfloat16(lo);
    }
}

__global__ void k_offsets() {
    if (threadIdx.x == 0) {
        int s = 0;
        for (int c = 0; c < NCLS; c++) { g_off[c] = s; g_cur[c] = s; s += g_counts[c]; }
    }
}

__global__ void k_scatter() {
    int i = blockIdx.x * blockDim.x + threadIdx.x;
    if (i < NROWS) {
        int c = g_lbl[i];
        int p = atomicAdd(&g_cur[c], 1);
        g_idx[p] = i;
    }
}

// ======================= persistent mma.sync bf16-split GEMM ====================
// Single __syncthreads per K-chunk: loads for chunk pos+NS-1 are issued AFTER the
// top-of-iteration barrier, targeting buffer (pos-1)%NS whose compute all warps
// passed at that same barrier. Cross-tile chunk streaming keeps cp.async full.
template<int MT, int NT, int WR, int WC, int MINB, int NS>
__global__ __launch_bounds__(256, MINB)
void k_gemm_mma(const __nv_bfloat16* __restrict__ Ah, const __nv_bfloat16* __restrict__ Al,
                const __nv_bfloat16* __restrict__ Bh, const __nv_bfloat16* __restrict__ Bl,
                const float* __restrict__ bias, float* __restrict__ f32out,
                __nv_bfloat16* __restrict__ oh, __nv_bfloat16* __restrict__ ol,
                int K, int N, int act, int lgx, int ntiles, int layer) {
    constexpr int MI   = MT / (WR * 16);
    constexpr int WN   = NT / WC;
    constexpr int NW8  = WN / 8;
    constexpr int NJ   = WN / 16;
    constexpr int MW   = MT / WR;
    constexpr int STRB = 80;
    constexpr int ABY  = MT * STRB;
    constexpr int BBY  = NT * STRB;
    constexpr int OFF_AL = ABY;
    constexpr int OFF_BH = 2 * ABY;
    constexpr int OFF_BL = 2 * ABY + BBY;
    constexpr int BUFSZ  = 2 * ABY + 2 * BBY;

    extern __shared__ __align__(16) char smem[];
    const uint32_t sbase = smem_u32(smem);
    __shared__ int sh_tile;

    const int tid = threadIdx.x;
    const int wid = tid >> 5, lane = tid & 31;
    const int wr = wid / WC, wc = wid % WC;
    const int gxm = (1 << lgx) - 1;
    const int nch = K >> 5;

    if (tid == 0) sh_tile = atomicAdd(&g_ctr[layer], 1);
    __syncthreads();
    int cur = sh_tile;
    if (cur >= ntiles) return;

    auto load_chunk = [&](int ti, int kc, int buf) {
        const int bm = (ti >> lgx) * MT;
        const int bn = (ti & gxm) * NT;
        const int k0 = kc << 5;
        const uint32_t sb = sbase + buf * BUFSZ;
        for (int u = tid; u < MT * 4; u += 256) {
            int r = u >> 2, s = u & 3;
            size_t go = (size_t)(bm + r) * K + k0 + s * 8;
            uint32_t so = (uint32_t)(r * STRB + s * 16);
            ld16(sb + so, Ah + go);
            ld16(sb + OFF_AL + so, Al + go);
        }
        for (int u = tid; u < NT * 4; u += 256) {
            int r = u >> 2, s = u & 3;
            size_t go = (size_t)(bn + r) * K + k0 + s * 8;
            uint32_t so = (uint32_t)(r * STRB + s * 16);
            ld16(sb + OFF_BH + so, Bh + go);
            ld16(sb + OFF_BL + so, Bl + go);
        }
        asm volatile("cp.async.commit_group;" ::: "memory");
    };

    // prologue: NS-1 chunks of the first tile (requires nch >= NS-1)
#pragma unroll
    for (int p = 0; p < NS - 1; p++) load_chunk(cur, p, p);

    int pos = 0;
    while (true) {
        float acc[MI][NW8][4];
#pragma unroll
        for (int a = 0; a < MI; a++)
#pragma unroll
            for (int b = 0; b < NW8; b++)
#pragma unroll
                for (int c = 0; c < 4; c++) acc[a][b][c] = 0.f;

        int nxt = ntiles;
        for (int kc = 0; kc < nch; kc++) {
            // oldest outstanding group = chunk pos -> ready after this wait
            asm volatile("cp.async.wait_group %0;" :: "n"(NS - 2));
            __syncthreads();

            // issue load for virtual chunk pos+NS-1 into buffer (pos-1)%NS
            const int lk = kc + NS - 1;
            const int lbuf = (pos + NS - 1) % NS;
            if (lk < nch) {
                load_chunk(cur, lk, lbuf);
            } else {
                if (lk == nch) {
                    if (tid == 0) sh_tile = atomicAdd(&g_ctr[layer], 1);
                    __syncthreads();
                    nxt = sh_tile;
                }
                if (nxt < ntiles) load_chunk(nxt, lk - nch, lbuf);
                else asm volatile("cp.async.commit_group;" ::: "memory");
            }

            const uint32_t sb = sbase + (pos % NS) * BUFSZ;
#pragma unroll
            for (int ks = 0; ks < 2; ks++) {
                uint32_t ah[MI][4], alr[MI][4];
#pragma unroll
                for (int mi = 0; mi < MI; mi++) {
                    uint32_t ar = wr * MW + mi * 16 + (lane & 15);
                    uint32_t ac = ks * 16 + (lane >> 4) * 8;
                    uint32_t ad = sb + ar * STRB + ac * 2;
                    ldsm4(ah[mi], ad);
                    ldsm4(alr[mi], ad + OFF_AL);
                }
                uint32_t br = wc * WN + ((lane >> 4) << 3) + (lane & 7);
                uint32_t bc = ks * 16 + ((lane >> 3) & 1) * 8;
#pragma unroll
                for (int nj = 0; nj < NJ; nj++) {
                    uint32_t bd = sb + OFF_BH + (br + nj * 16) * STRB + bc * 2;
                    uint32_t t[4], u4[4];
                    ldsm4(t, bd);
                    ldsm4(u4, bd + (OFF_BL - OFF_BH));
#pragma unroll
                    for (int mi = 0; mi < MI; mi++) {
                        mma16816(acc[mi][2 * nj],     ah[mi], t);
                        mma16816(acc[mi][2 * nj + 1], ah[mi], t + 2);
                    }
#pragma unroll
                    for (int mi = 0; mi < MI; mi++) {
                        mma16816(acc[mi][2 * nj],     ah[mi], u4);
                        mma16816(acc[mi][2 * nj + 1], ah[mi], u4 + 2);
                    }
#pragma unroll
                    for (int mi = 0; mi < MI; mi++) {
                        mma16816(acc[mi][2 * nj],     alr[mi], t);
                        mma16816(acc[mi][2 * nj + 1], alr[mi], t + 2);
                    }
                }
            }
            pos++;
        }

        // epilogue for cur (register -> global; overlaps next-tile loads in flight)
        {
            const int bm = (cur >> lgx) * MT;
            const int bn = (cur & gxm) * NT;
            const int g = lane >> 2, i2 = (lane & 3) * 2;
#pragma unroll
            for (int mi = 0; mi < MI; mi++) {
#pragma unroll
                for (int ni = 0; ni < NW8; ni++) {
                    int col = bn + wc * WN + ni * 8 + i2;
                    float b0 = bias[col], b1 = bias[col + 1];
#pragma unroll
                    for (int h = 0; h < 2; h++) {
                        int row = bm + wr * MW + mi * 16 + g + h * 8;
                        float v0 = acc[mi][ni][2 * h] + b0;
                        float v1 = acc[mi][ni][2 * h + 1] + b1;
                        if (act) { v0 = tanhf(v0); v1 = tanhf(v1); }
                        size_t oi = (size_t)row * N + col;
                        if (f32out) *(float2*)(f32out + oi) = make_float2(v0, v1);
                        if (oh) {
                            __nv_bfloat16 h0 = __float2bfloat16(v0);
                            __nv_bfloat16 h1 = __float2bfloat16(v1);
                            float l0 = v0 - __bfloat162float(h0);
                            float l1 = v1 - __bfloat162float(h1);
                            *(__nv_bfloat162*)(oh + oi) = __halves2bfloat162(h0, h1);
                            *(__nv_bfloat162*)(ol + oi) =
                                __halves2bfloat162(__float2bfloat16(l0), __float2bfloat16(l1));
                        }
                    }
                }
            }
        }
        if (nxt >= ntiles) return;
        cur = nxt;
    }
}

// ======================= fused per-class stats: sq, Q, S ========================
__global__ __launch_bounds__(256)
void k_stats() {
    __shared__ double sS[8][64];
    __shared__ double sQ[8];
    const int c = blockIdx.x;
    const int n = g_counts[c], off = g_off[c];
    const int w = threadIdx.x >> 5, lane = threadIdx.x & 31;

    double s0 = 0.0, s1 = 0.0, q = 0.0;
    for (int r = w; r < n; r += 8) {
        int row = g_idx[off + r];
        const float* e = g_emb + row * EMBD + 2;
        float v0 = e[lane];
        float v1 = (lane < NCON - 32) ? e[lane + 32] : 0.f;
        s0 += (double)v0;
        s1 += (double)v1;
        float sq = v0 * v0 + v1 * v1;
#pragma unroll
        for (int o = 16; o; o >>= 1) sq += __shfl_xor_sync(0xffffffff, sq, o);
        if (lane == 0) { g_sq[row] = sq; q += (double)sq; }
    }
    sS[w][lane] = s0;
    sS[w][lane + 32] = s1;
    if (lane == 0) sQ[w] = q;
    __syncthreads();
    int d = threadIdx.x;
    if (d < NCON) {
        double s = 0.0;
        for (int k = 0; k < 8; k++) s += sS[k][d];
        g_S[c * NCON + d] = s;
    }
    if (d == 64) {
        double s = 0.0;
        for (int k = 0; k < 8; k++) s += sQ[k];
        g_Q[c] = s;
    }
}

// ======================= same-class pairwise hinge (triangular) =================
__global__ __launch_bounds__(256)
void k_pairs() {
    const int c   = blockIdx.y;
    const int n   = g_counts[c];
    const int off = g_off[c];
    const int nt  = (n + 63) >> 6;
    const int tot = nt * (nt + 1) / 2;

    __shared__ float  smA[NCON][68];
    __shared__ float  smB[NCON][68];
    __shared__ float  sqA[64], sqB[64];
    __shared__ double red[256];

    const int tid = threadIdx.x;
    const int ty  = tid >> 4, tx = tid & 15;
    double acc = 0.0;

    for (int t = blockIdx.x; t < tot; t += gridDim.x) {
        int rem = t, TI = 0;
        while (rem >= nt - TI) { rem -= nt - TI; TI++; }
        int TJ = TI + rem;
        float w = (TI == TJ) ? 1.0f : 2.0f;
        int i0 = TI * 64, j0 = TJ * 64;
        __syncthreads();
        for (int e = tid; e < 64 * 64; e += 256) {
            int r = e >> 6, d = e & 63;
            if (d < NCON) {
                int ri = i0 + r, rj = j0 + r;
                smA[d][r] = (ri < n) ? g_emb[g_idx[off + ri] * EMBD + 2 + d] : 0.f;
                smB[d][r] = (rj < n) ? g_emb[g_idx[off + rj] * EMBD + 2 + d] : 0.f;
            }
        }
        if (tid < 64) {
            sqA[tid] = (i0 + tid < n) ? g_sq[g_idx[off + i0 + tid]] : 1e30f;
            sqB[tid] = (j0 + tid < n) ? g_sq[g_idx[off + j0 + tid]] : 1e30f;
        }
        __syncthreads();
        float dot[4][4] = {};
#pragma unroll
        for (int k = 0; k < NCON; k++) {
            float a[4], b[4];
#pragma unroll
            for (int i = 0; i < 4; i++) a[i] = smA[k][ty * 4 + i];
#pragma unroll
            for (int j = 0; j < 4; j++) b[j] = smB[k][tx * 4 + j];
#pragma unroll
            for (int i = 0; i < 4; i++)
#pragma unroll
                for (int j = 0; j < 4; j++) dot[i][j] += a[i] * b[j];
        }
        float ts = 0.f;
#pragma unroll
        for (int i = 0; i < 4; i++) {
            float si = sqA[ty * 4 + i];
#pragma unroll
            for (int j = 0; j < 4; j++) {
                float df = si + sqB[tx * 4 + j] - 2.f * dot[i][j];
                float dm = fmaxf(df, 0.f) * (1.0f / 62.0f);
                ts += fmaxf(0.f, MARGINF - dm);
            }
        }
        acc += (double)(w * ts);
    }
    red[tid] = acc;
    __syncthreads();
    for (int o = 128; o; o >>= 1) {
        if (tid < o) red[tid] += red[tid + o];
        __syncthreads();
    }
    if (tid == 0 && red[0] != 0.0) atomicAdd(&g_cdiff, red[0]);
}

// ======================= finalize scalars =======================================
__global__ void k_final(float* __restrict__ out) {
    __shared__ double shA[64], shB[64];
    int d = threadIdx.x;
    double sgd = 0.0, s2c = 0.0;
    if (d < NCON) {
        for (int c = 0; c < NCLS; c++) {
            double v = g_S[c * NCON + d];
            sgd += v;
            s2c += v * v;
        }
    }
    shA[d] = sgd * sgd;
    shB[d] = s2c;
    __syncthreads();
    if (d == 0) {
        double S2g = 0.0, S2c = 0.0;
        for (int k = 0; k < 64; k++) { S2g += shA[k]; S2c += shB[k]; }
        double T = 0.0, sumn2 = 0.0, snq = 0.0;
        for (int c = 0; c < NCLS; c++) {
            double nc = (double)g_counts[c];
            T     += g_Q[c];
            sumn2 += nc * nc;
            snq   += 2.0 * nc * g_Q[c];
        }
        double Nd     = (double)NROWS;
        double n_diff = Nd * Nd - sumn2;
        double sum_all  = 2.0 * Nd * T - 2.0 * S2g;
        double sum_same = snq - 2.0 * S2c;
        double C_sim  = (sum_all - sum_same) / 62.0 / (n_diff + 1.0);
        double C_diff = g_cdiff / (Nd * Nd - n_diff + 1.0);
        out[OUT_OFF + 0] = (float)C_sim;
        out[OUT_OFF + 1] = (float)C_diff;
    }
}

// ======================= launch =================================================
extern "C" void kernel_launch(void* const* d_in, const int* in_sizes, int n_in,
                              void* d_out, int out_size) {
    const float* x  = (const float*)d_in[0];
    const float* W1 = (const float*)d_in[1];
    const float* b1 = (const float*)d_in[2];
    const float* W2 = (const float*)d_in[3];
    const float* b2 = (const float*)d_in[4];
    const float* W3 = (const float*)d_in[5];
    const float* b3 = (const float*)d_in[6];
    const float* W4 = (const float*)d_in[7];
    const float* b4 = (const float*)d_in[8];
    float* out = (float*)d_out;

    // L1/L4: 128x64 tile, 3 CTAs/SM, 2-stage -> 61440B
    cudaFuncSetAttribute((const void*)k_gemm_mma<128, 64, 4, 2, 3, 2>,
                         cudaFuncAttributeMaxDynamicSharedMemorySize, 61440);
    // L3: 64x64 tile, 4 CTAs/SM, 2-stage -> 40960B
    cudaFuncSetAttribute((const void*)k_gemm_mma<64, 64, 4, 2, 4, 2>,
                         cudaFuncAttributeMaxDynamicSharedMemorySize, 40960);
    // L2: 64x32 tile, 3 CTAs/SM, 4-stage -> 61440B
    cudaFuncSetAttribute((const void*)k_gemm_mma<64, 32, 4, 2, 3, 4>,
                         cudaFuncAttributeMaxDynamicSharedMemorySize, 61440);

    __nv_bfloat16 *dh, *dl, *h1h, *h1l, *eh, *el, *h2h, *h2l;
    __nv_bfloat16 *w1h, *w1l, *w2h, *w2l, *w3h, *w3l, *w4h, *w4l;
    float* pemb;
    cudaGetSymbolAddress((void**)&dh,  g_data_h); cudaGetSymbolAddress((void**)&dl,  g_data_l);
    cudaGetSymbolAddress((void**)&h1h, g_h1_h);   cudaGetSymbolAddress((void**)&h1l, g_h1_l);
    cudaGetSymbolAddress((void**)&eh,  g_emb_h);  cudaGetSymbolAddress((void**)&el,  g_emb_l);
    cudaGetSymbolAddress((void**)&h2h, g_h2_h);   cudaGetSymbolAddress((void**)&h2l, g_h2_l);
    cudaGetSymbolAddress((void**)&w1h, g_w1_h);   cudaGetSymbolAddress((void**)&w1l, g_w1_l);
    cudaGetSymbolAddress((void**)&w2h, g_w2_h);   cudaGetSymbolAddress((void**)&w2l, g_w2_l);
    cudaGetSymbolAddress((void**)&w3h, g_w3_h);   cudaGetSymbolAddress((void**)&w3l, g_w3_l);
    cudaGetSymbolAddress((void**)&w4h, g_w4_h);   cudaGetSymbolAddress((void**)&w4l, g_w4_l);
    cudaGetSymbolAddress((void**)&pemb, g_emb);

    k_init<<<1, 1024>>>();                                   // my #0
    k_prep<<<4096, 256>>>(x);                                // my #1
    k_wt_all<<<2304, 256>>>(W1, W2, W3, W4);                 // my #2

    // L1: h1 = tanh(data @ W1 + b1)  [8192,1024], K=512 --- my #3 (ncu target)
    k_gemm_mma<128, 64, 4, 2, 3, 2><<<456, 256, 61440>>>(
        dh, dl, w1h, w1l, b1, nullptr, h1h, h1l, DIN, HID, 1, 4, 1024, 0);

    k_offsets<<<1, 32>>>();
    k_scatter<<<32, 256>>>();

    // L2: emb = h1 @ W2 + b2  [8192,64], K=1024 -- 256 tiles (gx=2), 4-stage
    k_gemm_mma<64, 32, 4, 2, 3, 4><<<456, 256, 61440>>>(
        h1h, h1l, w2h, w2l, b2, pemb, eh, el, HID, EMBD, 0, 1, 256, 1);
    k_stats<<<NCLS, 256>>>();
    // L3: h2 = tanh(emb @ W3 + b3)  [8192,1024], K=64 -- 2048 tiles (gx=16)
    k_gemm_mma<64, 64, 4, 2, 4, 2><<<608, 256, 40960>>>(
        eh, el, w3h, w3l, b3, nullptr, h2h, h2l, EMBD, HID, 1, 4, 2048, 2);
    // L4: decoded = h2 @ W4 + b4 -> d_out  [8192,512], K=1024 -- 512 tiles (gx=8)
    k_gemm_mma<128, 64, 4, 2, 3, 2><<<456, 256, 61440>>>(
        h2h, h2l, w4h, w4l, b4, out, nullptr, nullptr, HID, DIN, 0, 3, 512, 3);

    k_pairs<<<dim3(40, NCLS), 256>>>();
    k_final<<<1, 64>>>(out);
}

// round 16
// speedup vs baseline: 1.0262x; 1.0262x over previous
#include <cuda_runtime.h>
#include <cuda_bf16.h>
#include <cstdint>
#include <math.h>

#define NROWS 8192
#define DIN   512
#define HID   1024
#define EMBD  64
#define NCON  62
#define NCLS  16
#define MARGINF 0.01f
#define OUT_OFF (NROWS * DIN)

// ======================= helpers ================================================
__device__ __forceinline__ void ld16(uint32_t s, const void* g) {
    asm volatile("cp.async.cg.shared.global [%0], [%1], 16;" :: "r"(s), "l"(g));
}
__device__ __forceinline__ uint32_t smem_u32(const void* p) {
    uint32_t a;
    asm("{ .reg .u64 t; cvta.to.shared.u64 t, %1; cvt.u32.u64 %0, t; }" : "=r"(a) : "l"(p));
    return a;
}
__device__ __forceinline__ void ldsm4(uint32_t* r, uint32_t addr) {
    asm volatile("ldmatrix.sync.aligned.m8n8.x4.shared.b16 {%0,%1,%2,%3}, [%4];"
        : "=r"(r[0]), "=r"(r[1]), "=r"(r[2]), "=r"(r[3]) : "r"(addr));
}
__device__ __forceinline__ void mma16816(float* c, const uint32_t* a, const uint32_t* b) {
    asm volatile("mma.sync.aligned.m16n8k16.row.col.f32.bf16.bf16.f32 "
        "{%0,%1,%2,%3}, {%4,%5,%6,%7}, {%8,%9}, {%0,%1,%2,%3};"
        : "+f"(c[0]), "+f"(c[1]), "+f"(c[2]), "+f"(c[3])
        : "r"(a[0]), "r"(a[1]), "r"(a[2]), "r"(a[3]), "r"(b[0]), "r"(b[1]));
}

// ======================= scratch (device globals) ===============================
__device__ __nv_bfloat16 g_data_h[NROWS * DIN],  g_data_l[NROWS * DIN];
__device__ __nv_bfloat16 g_h1_h[NROWS * HID],    g_h1_l[NROWS * HID];
__device__ __nv_bfloat16 g_emb_h[NROWS * EMBD],  g_emb_l[NROWS * EMBD];
__device__ __nv_bfloat16 g_h2_h[NROWS * HID],    g_h2_l[NROWS * HID];
__device__ __nv_bfloat16 g_w1_h[HID * DIN],  g_w1_l[HID * DIN];    // [N,K]
__device__ __nv_bfloat16 g_w2_h[EMBD * HID], g_w2_l[EMBD * HID];
__device__ __nv_bfloat16 g_w3_h[HID * EMBD], g_w3_l[HID * EMBD];
__device__ __nv_bfloat16 g_w4_h[DIN * HID],  g_w4_l[DIN * HID];
__device__ float  g_emb[NROWS * EMBD];
__device__ int    g_lbl[NROWS];
__device__ float  g_sq[NROWS];
__device__ int    g_counts[NCLS], g_off[NCLS], g_cur[NCLS], g_idx[NROWS];
__device__ double g_S[NCLS * NCON];
__device__ double g_Q[NCLS];
__device__ double g_cdiff;
__device__ int    g_ctr[8];   // per-layer persistent tile counters

// ======================= small kernels ==========================================
__global__ void k_init() {
    int t = threadIdx.x;
    if (t < NCLS) { g_counts[t] = 0; g_Q[t] = 0.0; }
    if (t < 8) g_ctr[t] = 0;
    if (t == 0) g_cdiff = 0.0;
    for (int i = t; i < NCLS * NCON; i += blockDim.x) g_S[i] = 0.0;
}

__global__ void k_prep(const float* __restrict__ x) {
    const int total = NROWS * (DIN + 1);
    for (int e = blockIdx.x * blockDim.x + threadIdx.x; e < total;
         e += gridDim.x * blockDim.x) {
        int i = e / (DIN + 1);
        int j = e - i * (DIN + 1);
        float v = x[e];
        if (j == 0) {
            int c = (int)v;
            g_lbl[i] = c;
            atomicAdd(&g_counts[c], 1);
        } else {
            __nv_bfloat16 h = __float2bfloat16(v);
            float lo = v - __bfloat162float(h);
            int idx = i * DIN + (j - 1);
            g_data_h[idx] = h;
            g_data_l[idx] = __float2bfloat16(lo);
        }
    }
}

// transpose + split all four weight matrices W[K,N] -> [N,K] bf16 hi/lo
__global__ void k_wt_all(const float* __restrict__ W1, const float* __restrict__ W2,
                         const float* __restrict__ W3, const float* __restrict__ W4) {
    const int S1 = DIN * HID, S2 = HID * EMBD, S3 = EMBD * HID, S4 = HID * DIN;
    const int T1 = S1, T2 = T1 + S2, T3 = T2 + S3, T4 = T3 + S4;
    for (int e = blockIdx.x * blockDim.x + threadIdx.x; e < T4;
         e += gridDim.x * blockDim.x) {
        const float* W;
        __nv_bfloat16 *th, *tl;
        int le, K, N;
        if (e < T1)      { W = W1; th = g_w1_h; tl = g_w1_l; le = e;      K = DIN;  N = HID;  }
        else if (e < T2) { W = W2; th = g_w2_h; tl = g_w2_l; le = e - T1; K = HID;  N = EMBD; }
        else if (e < T3) { W = W3; th = g_w3_h; tl = g_w3_l; le = e - T2; K = EMBD; N = HID;  }
        else             { W = W4; th = g_w4_h; tl = g_w4_l; le = e - T3; K = HID;  N = DIN;  }
        int k = le / N, n = le - k * N;
        float v = W[le];
        __nv_bfloat16 h = __float2bfloat16(v);
        float lo = v - __bfloat162float(h);
        th[n * K + k] = h;
        tl[n * K + k] = __float2bfloat16(lo);
    }
}

__global__ void k_offsets() {
    if (threadIdx.x == 0) {
        int s = 0;
        for (int c = 0; c < NCLS; c++) { g_off[c] = s; g_cur[c] = s; s += g_counts[c]; }
    }
}

__global__ void k_scatter() {
    int i = blockIdx.x * blockDim.x + threadIdx.x;
    if (i < NROWS) {
        int c = g_lbl[i];
        int p = atomicAdd(&g_cur[c], 1);
        g_idx[p] = i;
    }
}

// ======================= persistent mma.sync bf16-split GEMM ====================
// Tiles popped from g_ctr[layer]; continuous cross-tile chunk stream keeps the
// NS-stage cp.async pipeline full across tile boundaries.
template<int MT, int NT, int WR, int WC, int MINB, int NS>
__global__ __launch_bounds__(256, MINB)
void k_gemm_mma(const __nv_bfloat16* __restrict__ Ah, const __nv_bfloat16* __restrict__ Al,
                const __nv_bfloat16* __restrict__ Bh, const __nv_bfloat16* __restrict__ Bl,
                const float* __restrict__ bias, float* __restrict__ f32out,
                __nv_bfloat16* __restrict__ oh, __nv_bfloat16* __restrict__ ol,
                int K, int N, int act, int lgx, int ntiles, int layer) {
    constexpr int MI   = MT / (WR * 16);
    constexpr int WN   = NT / WC;
    constexpr int NW8  = WN / 8;
    constexpr int NJ   = WN / 16;
    constexpr int MW   = MT / WR;
    constexpr int STRB = 80;
    constexpr int ABY  = MT * STRB;
    constexpr int BBY  = NT * STRB;
    constexpr int OFF_AL = ABY;
    constexpr int OFF_BH = 2 * ABY;
    constexpr int OFF_BL = 2 * ABY + BBY;
    constexpr int BUFSZ  = 2 * ABY + 2 * BBY;

    extern __shared__ __align__(16) char smem[];
    const uint32_t sbase = smem_u32(smem);
    __shared__ int sh_tile;

    const int tid = threadIdx.x;
    const int wid = tid >> 5, lane = tid & 31;
    const int wr = wid / WC, wc = wid % WC;
    const int gxm = (1 << lgx) - 1;
    const int nch = K >> 5;

    if (tid == 0) sh_tile = atomicAdd(&g_ctr[layer], 1);
    __syncthreads();
    int cur = sh_tile;
    if (cur >= ntiles) return;

    auto load_chunk = [&](int ti, int kc, int buf) {
        const int bm = (ti >> lgx) * MT;
        const int bn = (ti & gxm) * NT;
        const int k0 = kc << 5;
        const uint32_t sb = sbase + buf * BUFSZ;
        for (int u = tid; u < MT * 4; u += 256) {
            int r = u >> 2, s = u & 3;
            size_t go = (size_t)(bm + r) * K + k0 + s * 8;
            uint32_t so = (uint32_t)(r * STRB + s * 16);
            ld16(sb + so, Ah + go);
            ld16(sb + OFF_AL + so, Al + go);
        }
        for (int u = tid; u < NT * 4; u += 256) {
            int r = u >> 2, s = u & 3;
            size_t go = (size_t)(bn + r) * K + k0 + s * 8;
            uint32_t so = (uint32_t)(r * STRB + s * 16);
            ld16(sb + OFF_BH + so, Bh + go);
            ld16(sb + OFF_BL + so, Bl + go);
        }
        asm volatile("cp.async.commit_group;" ::: "memory");
    };

    // prologue: NS-1 chunks of the first tile (requires nch >= NS-1)
#pragma unroll
    for (int p = 0; p < NS - 1; p++) load_chunk(cur, p, p);

    int pos = 0;
    while (true) {
        float acc[MI][NW8][4];
#pragma unroll
        for (int a = 0; a < MI; a++)
#pragma unroll
            for (int b = 0; b < NW8; b++)
#pragma unroll
                for (int c = 0; c < 4; c++) acc[a][b][c] = 0.f;

        int nxt = ntiles;
        for (int kc = 0; kc < nch; kc++) {
            const int lk = kc + NS - 1;
            const int lbuf = (pos + NS - 1) % NS;
            if (lk < nch) {
                load_chunk(cur, lk, lbuf);
            } else {
                if (lk == nch) {
                    if (tid == 0) sh_tile = atomicAdd(&g_ctr[layer], 1);
                    __syncthreads();
                    nxt = sh_tile;
                }
                if (nxt < ntiles) load_chunk(nxt, lk - nch, lbuf);
                else asm volatile("cp.async.commit_group;" ::: "memory");
            }
            asm volatile("cp.async.wait_group %0;" :: "n"(NS - 1));
            __syncthreads();

            const uint32_t sb = sbase + (pos % NS) * BUFSZ;
#pragma unroll
            for (int ks = 0; ks < 2; ks++) {
                uint32_t ah[MI][4], alr[MI][4];
#pragma unroll
                for (int mi = 0; mi < MI; mi++) {
                    uint32_t ar = wr * MW + mi * 16 + (lane & 15);
                    uint32_t ac = ks * 16 + (lane >> 4) * 8;
                    uint32_t ad = sb + ar * STRB + ac * 2;
                    ldsm4(ah[mi], ad);
                    ldsm4(alr[mi], ad + OFF_AL);
                }
                uint32_t br = wc * WN + ((lane >> 4) << 3) + (lane & 7);
                uint32_t bc = ks * 16 + ((lane >> 3) & 1) * 8;
#pragma unroll
                for (int nj = 0; nj < NJ; nj++) {
                    uint32_t bd = sb + OFF_BH + (br + nj * 16) * STRB + bc * 2;
                    uint32_t t[4], u4[4];
                    ldsm4(t, bd);
                    ldsm4(u4, bd + (OFF_BL - OFF_BH));
#pragma unroll
                    for (int mi = 0; mi < MI; mi++) {
                        mma16816(acc[mi][2 * nj],     ah[mi], t);
                        mma16816(acc[mi][2 * nj + 1], ah[mi], t + 2);
                    }
#pragma unroll
                    for (int mi = 0; mi < MI; mi++) {
                        mma16816(acc[mi][2 * nj],     ah[mi], u4);
                        mma16816(acc[mi][2 * nj + 1], ah[mi], u4 + 2);
                    }
#pragma unroll
                    for (int mi = 0; mi < MI; mi++) {
                        mma16816(acc[mi][2 * nj],     alr[mi], t);
                        mma16816(acc[mi][2 * nj + 1], alr[mi], t + 2);
                    }
                }
            }
            __syncthreads();
            pos++;
        }

        // epilogue for cur (register -> global; overlaps next-tile loads in flight)
        {
            const int bm = (cur >> lgx) * MT;
            const int bn = (cur & gxm) * NT;
            const int g = lane >> 2, i2 = (lane & 3) * 2;
#pragma unroll
            for (int mi = 0; mi < MI; mi++) {
#pragma unroll
                for (int ni = 0; ni < NW8; ni++) {
                    int col = bn + wc * WN + ni * 8 + i2;
                    float b0 = bias[col], b1 = bias[col + 1];
#pragma unroll
                    for (int h = 0; h < 2; h++) {
                        int row = bm + wr * MW + mi * 16 + g + h * 8;
                        float v0 = acc[mi][ni][2 * h] + b0;
                        float v1 = acc[mi][ni][2 * h + 1] + b1;
                        if (act) { v0 = tanhf(v0); v1 = tanhf(v1); }
                        size_t oi = (size_t)row * N + col;
                        if (f32out) *(float2*)(f32out + oi) = make_float2(v0, v1);
                        if (oh) {
                            __nv_bfloat16 h0 = __float2bfloat16(v0);
                            __nv_bfloat16 h1 = __float2bfloat16(v1);
                            float l0 = v0 - __bfloat162float(h0);
                            float l1 = v1 - __bfloat162float(h1);
                            *(__nv_bfloat162*)(oh + oi) = __halves2bfloat162(h0, h1);
                            *(__nv_bfloat162*)(ol + oi) =
                                __halves2bfloat162(__float2bfloat16(l0), __float2bfloat16(l1));
                        }
                    }
                }
            }
        }
        if (nxt >= ntiles) return;
        cur = nxt;
    }
}

// ======================= fused per-class stats: sq, Q, S ========================
__global__ __launch_bounds__(256)
void k_stats() {
    __shared__ double sS[8][64];
    __shared__ double sQ[8];
    const int c = blockIdx.x;
    const int n = g_counts[c], off = g_off[c];
    const int w = threadIdx.x >> 5, lane = threadIdx.x & 31;

    double s0 = 0.0, s1 = 0.0, q = 0.0;
    for (int r = w; r < n; r += 8) {
        int row = g_idx[off + r];
        const float* e = g_emb + row * EMBD + 2;
        float v0 = e[lane];
        float v1 = (lane < NCON - 32) ? e[lane + 32] : 0.f;
        s0 += (double)v0;
        s1 += (double)v1;
        float sq = v0 * v0 + v1 * v1;
#pragma unroll
        for (int o = 16; o; o >>= 1) sq += __shfl_xor_sync(0xffffffff, sq, o);
        if (lane == 0) { g_sq[row] = sq; q += (double)sq; }
    }
    sS[w][lane] = s0;
    sS[w][lane + 32] = s1;
    if (lane == 0) sQ[w] = q;
    __syncthreads();
    int d = threadIdx.x;
    if (d < NCON) {
        double s = 0.0;
        for (int k = 0; k < 8; k++) s += sS[k][d];
        g_S[c * NCON + d] = s;
    }
    if (d == 64) {
        double s = 0.0;
        for (int k = 0; k < 8; k++) s += sQ[k];
        g_Q[c] = s;
    }
}

// ======================= same-class pairwise hinge (triangular) =================
__global__ __launch_bounds__(256)
void k_pairs() {
    const int c   = blockIdx.y;
    const int n   = g_counts[c];
    const int off = g_off[c];
    const int nt  = (n + 63) >> 6;
    const int tot = nt * (nt + 1) / 2;

    __shared__ float  smA[NCON][68];
    __shared__ float  smB[NCON][68];
    __shared__ float  sqA[64], sqB[64];
    __shared__ double red[256];

    const int tid = threadIdx.x;
    const int ty  = tid >> 4, tx = tid & 15;
    double acc = 0.0;

    for (int t = blockIdx.x; t < tot; t += gridDim.x) {
        int rem = t, TI = 0;
        while (rem >= nt - TI) { rem -= nt - TI; TI++; }
        int TJ = TI + rem;
        float w = (TI == TJ) ? 1.0f : 2.0f;
        int i0 = TI * 64, j0 = TJ * 64;
        __syncthreads();
        for (int e = tid; e < 64 * 64; e += 256) {
            int r = e >> 6, d = e & 63;
            if (d < NCON) {
                int ri = i0 + r, rj = j0 + r;
                smA[d][r] = (ri < n) ? g_emb[g_idx[off + ri] * EMBD + 2 + d] : 0.f;
                smB[d][r] = (rj < n) ? g_emb[g_idx[off + rj] * EMBD + 2 + d] : 0.f;
            }
        }
        if (tid < 64) {
            sqA[tid] = (i0 + tid < n) ? g_sq[g_idx[off + i0 + tid]] : 1e30f;
            sqB[tid] = (j0 + tid < n) ? g_sq[g_idx[off + j0 + tid]] : 1e30f;
        }
        __syncthreads();
        float dot[4][4] = {};
#pragma unroll
        for (int k = 0; k < NCON; k++) {
            float a[4], b[4];
#pragma unroll
            for (int i = 0; i < 4; i++) a[i] = smA[k][ty * 4 + i];
#pragma unroll
            for (int j = 0; j < 4; j++) b[j] = smB[k][tx * 4 + j];
#pragma unroll
            for (int i = 0; i < 4; i++)
#pragma unroll
                for (int j = 0; j < 4; j++) dot[i][j] += a[i] * b[j];
        }
        float ts = 0.f;
#pragma unroll
        for (int i = 0; i < 4; i++) {
            float si = sqA[ty * 4 + i];
#pragma unroll
            for (int j = 0; j < 4; j++) {
                float df = si + sqB[tx * 4 + j] - 2.f * dot[i][j];
                float dm = fmaxf(df, 0.f) * (1.0f / 62.0f);
                ts += fmaxf(0.f, MARGINF - dm);
            }
        }
        acc += (double)(w * ts);
    }
    red[tid] = acc;
    __syncthreads();
    for (int o = 128; o; o >>= 1) {
        if (tid < o) red[tid] += red[tid + o];
        __syncthreads();
    }
    if (tid == 0 && red[0] != 0.0) atomicAdd(&g_cdiff, red[0]);
}

// ======================= finalize scalars =======================================
__global__ void k_final(float* __restrict__ out) {
    __shared__ double shA[64], shB[64];
    int d = threadIdx.x;
    double sgd = 0.0, s2c = 0.0;
    if (d < NCON) {
        for (int c = 0; c < NCLS; c++) {
            double v = g_S[c * NCON + d];
            sgd += v;
            s2c += v * v;
        }
    }
    shA[d] = sgd * sgd;
    shB[d] = s2c;
    __syncthreads();
    if (d == 0) {
        double S2g = 0.0, S2c = 0.0;
        for (int k = 0; k < 64; k++) { S2g += shA[k]; S2c += shB[k]; }
        double T = 0.0, sumn2 = 0.0, snq = 0.0;
        for (int c = 0; c < NCLS; c++) {
            double nc = (double)g_counts[c];
            T     += g_Q[c];
            sumn2 += nc * nc;
            snq   += 2.0 * nc * g_Q[c];
        }
        double Nd     = (double)NROWS;
        double n_diff = Nd * Nd - sumn2;
        double sum_all  = 2.0 * Nd * T - 2.0 * S2g;
        double sum_same = snq - 2.0 * S2c;
        double C_sim  = (sum_all - sum_same) / 62.0 / (n_diff + 1.0);
        double C_diff = g_cdiff / (Nd * Nd - n_diff + 1.0);
        out[OUT_OFF + 0] = (float)C_sim;
        out[OUT_OFF + 1] = (float)C_diff;
    }
}

// ======================= launch =================================================
extern "C" void kernel_launch(void* const* d_in, const int* in_sizes, int n_in,
                              void* d_out, int out_size) {
    const float* x  = (const float*)d_in[0];
    const float* W1 = (const float*)d_in[1];
    const float* b1 = (const float*)d_in[2];
    const float* W2 = (const float*)d_in[3];
    const float* b2 = (const float*)d_in[4];
    const float* W3 = (const float*)d_in[5];
    const float* b3 = (const float*)d_in[6];
    const float* W4 = (const float*)d_in[7];
    const float* b4 = (const float*)d_in[8];
    float* out = (float*)d_out;

    // L1/L4: 128x64 tile, 3 CTAs/SM, 2-stage -> 61440B
    cudaFuncSetAttribute((const void*)k_gemm_mma<128, 64, 4, 2, 3, 2>,
                         cudaFuncAttributeMaxDynamicSharedMemorySize, 61440);
    // L3: 64x64 tile, 4 CTAs/SM, 2-stage -> 40960B
    cudaFuncSetAttribute((const void*)k_gemm_mma<64, 64, 4, 2, 4, 2>,
                         cudaFuncAttributeMaxDynamicSharedMemorySize, 40960);
    // L2: 64x32 tile, 2 CTAs/SM, 4-stage -> 61440B
    cudaFuncSetAttribute((const void*)k_gemm_mma<64, 32, 4, 2, 2, 4>,
                         cudaFuncAttributeMaxDynamicSharedMemorySize, 61440);

    __nv_bfloat16 *dh, *dl, *h1h, *h1l, *eh, *el, *h2h, *h2l;
    __nv_bfloat16 *w1h, *w1l, *w2h, *w2l, *w3h, *w3l, *w4h, *w4l;
    float* pemb;
    cudaGetSymbolAddress((void**)&dh,  g_data_h); cudaGetSymbolAddress((void**)&dl,  g_data_l);
    cudaGetSymbolAddress((void**)&h1h, g_h1_h);   cudaGetSymbolAddress((void**)&h1l, g_h1_l);
    cudaGetSymbolAddress((void**)&eh,  g_emb_h);  cudaGetSymbolAddress((void**)&el,  g_emb_l);
    cudaGetSymbolAddress((void**)&h2h, g_h2_h);   cudaGetSymbolAddress((void**)&h2l, g_h2_l);
    cudaGetSymbolAddress((void**)&w1h, g_w1_h);   cudaGetSymbolAddress((void**)&w1l, g_w1_l);
    cudaGetSymbolAddress((void**)&w2h, g_w2_h);   cudaGetSymbolAddress((void**)&w2l, g_w2_l);
    cudaGetSymbolAddress((void**)&w3h, g_w3_h);   cudaGetSymbolAddress((void**)&w3l, g_w3_l);
    cudaGetSymbolAddress((void**)&w4h, g_w4_h);   cudaGetSymbolAddress((void**)&w4l, g_w4_l);
    cudaGetSymbolAddress((void**)&pemb, g_emb);

    k_init<<<1, 1024>>>();                                   // my #0
    k_prep<<<4096, 256>>>(x);                                // my #1
    k_wt_all<<<2304, 256>>>(W1, W2, W3, W4);                 // my #2

    // L1: h1 = tanh(data @ W1 + b1)  [8192,1024], K=512 --- my #3 (ncu target)
    // 1024 tiles (gx=16), persistent grid 456
    k_gemm_mma<128, 64, 4, 2, 3, 2><<<456, 256, 61440>>>(
        dh, dl, w1h, w1l, b1, nullptr, h1h, h1l, DIN, HID, 1, 4, 1024, 0);

    k_offsets<<<1, 32>>>();
    k_scatter<<<32, 256>>>();

    // L2: emb = h1 @ W2 + b2  [8192,64], K=1024 -- 256 tiles (gx=2), 4-stage
    k_gemm_mma<64, 32, 4, 2, 2, 4><<<304, 256, 61440>>>(
        h1h, h1l, w2h, w2l, b2, pemb, eh, el, HID, EMBD, 0, 1, 256, 1);
    k_stats<<<NCLS, 256>>>();
    // L3: h2 = tanh(emb @ W3 + b3)  [8192,1024], K=64 -- 2048 tiles (gx=16)
    k_gemm_mma<64, 64, 4, 2, 4, 2><<<608, 256, 40960>>>(
        eh, el, w3h, w3l, b3, nullptr, h2h, h2l, EMBD, HID, 1, 4, 2048, 2);
    // L4: decoded = h2 @ W4 + b4 -> d_out  [8192,512], K=1024 -- 512 tiles (gx=8)
    k_gemm_mma<128, 64, 4, 2, 3, 2><<<456, 256, 61440>>>(
        h2h, h2l, w4h, w4l, b4, out, nullptr, nullptr, HID, DIN, 0, 3, 512, 3);

    k_pairs<<<dim3(40, NCLS), 256>>>();
    k_final<<<1, 64>>>(out);
}